// round 13
// baseline (speedup 1.0000x reference)
#include <cuda_runtime.h>
#include <cstdint>

#define NN   100000
#define TT   10
#define FF   64
#define EE   1600000
#define EDD  8
#define HH   128
#define BB   2048
#define CC   2
#define BN_EPS 1e-5f

// ---------------- device scratch (no allocations allowed) ----------------
__device__ __align__(16) float g_wcomb[128 * 128];            // [k][h], k<64: w_self, k>=64: w_msg x-part
__device__ __align__(16) float g_wlstm[256 * 512];            // [k][j] transposed concat(w_ih, w_hh)
__device__ __align__(16) float g_static[(size_t)NN * HH];     // time-invariant per-node term
__device__ __align__(16) float g_eattr[NN * EDD];             // per-node edge_attr sums
__device__ __align__(16) float g_agg[(size_t)NN * FF];        // per-step aggregated neighbor features
__device__ int   g_deg[NN];
__device__ int   g_rowoff[NN + 1];
__device__ int   g_cursor[NN];
__device__ int   g_csr_src[EE];
__device__ int   g_csr_eid[EE];
__device__ float g_stats[2 * HH];                             // sum, sumsq per channel
__device__ float g_stats_dummy[2 * HH];                       // sink for diagnostic dummy launch
__device__ float g_bnscale[HH], g_bnshift[HH];
__device__ __align__(16) float g_hseq[(size_t)TT * BB * HH];
__device__ __align__(16) float g_h[BB * HH];
__device__ __align__(16) float g_c[BB * HH];
__device__ __align__(16) float g_gates[(size_t)BB * 4 * HH];

// ---------------- f32x2 packed-FMA helpers (Blackwell FFMA2) ----------------
__device__ __forceinline__ unsigned long long pk2(float a, float b) {
    unsigned long long r;
    asm("mov.b64 %0, {%1, %2};" : "=l"(r) : "f"(a), "f"(b));
    return r;
}
__device__ __forceinline__ unsigned long long ffma2(unsigned long long a, unsigned long long b,
                                                    unsigned long long c) {
    unsigned long long d;
    asm("fma.rn.f32x2 %0, %1, %2, %3;" : "=l"(d) : "l"(a), "l"(b), "l"(c));
    return d;
}
__device__ __forceinline__ void upk2(unsigned long long v, float& a, float& b) {
    asm("mov.b64 {%0, %1}, %2;" : "=f"(a), "=f"(b) : "l"(v));
}

// ---------------- prep kernels ----------------
__global__ void zero_kernel() {
    int i = blockIdx.x * 256 + threadIdx.x;  // grid 1024 -> 262144 = BB*HH
    if (i < NN) { g_deg[i] = 0; g_cursor[i] = 0; }
    g_h[i] = 0.f;
    g_c[i] = 0.f;
    if (blockIdx.x == 0) g_stats[threadIdx.x] = 0.f;  // 256 stats entries
}

__global__ void deg_kernel(const int* __restrict__ ei) {
    int e = blockIdx.x * 256 + threadIdx.x;  // grid = E exactly
    int d = ei[EE + e];
    atomicAdd(&g_deg[d], 1);
}

__global__ void scan_kernel() {  // 1 block, 1024 threads
    const int CH = (NN + 1023) / 1024;  // 98
    int t = threadIdx.x;
    int beg = t * CH;
    int end = min(beg + CH, NN);
    int s = 0;
    for (int i = beg; i < end; i++) s += g_deg[i];
    __shared__ int ps[1024];
    ps[t] = s;
    __syncthreads();
    for (int off = 1; off < 1024; off <<= 1) {
        int v = (t >= off) ? ps[t - off] : 0;
        __syncthreads();
        ps[t] += v;
        __syncthreads();
    }
    int run = ps[t] - s;  // exclusive prefix of this chunk
    for (int i = beg; i < end; i++) { g_rowoff[i] = run; run += g_deg[i]; }
    if (t == 1023) g_rowoff[NN] = ps[1023];
}

__global__ void fill_kernel(const int* __restrict__ ei) {
    int e = blockIdx.x * 256 + threadIdx.x;  // grid = E exactly
    int d = ei[EE + e];
    int pos = g_rowoff[d] + atomicAdd(&g_cursor[d], 1);
    g_csr_src[pos] = ei[e];
    g_csr_eid[pos] = e;
}

__global__ void eattr_kernel(const float* __restrict__ eattr) {
    int n = blockIdx.x * 256 + threadIdx.x;
    if (n >= NN) return;
    float s[EDD];
#pragma unroll
    for (int j = 0; j < EDD; j++) s[j] = 0.f;
    int beg = g_rowoff[n], end = g_rowoff[n + 1];
    for (int e = beg; e < end; e++) {
        int id = g_csr_eid[e];
        const float4* p = (const float4*)(eattr + (size_t)id * EDD);
        float4 a = p[0], b = p[1];
        s[0] += a.x; s[1] += a.y; s[2] += a.z; s[3] += a.w;
        s[4] += b.x; s[5] += b.y; s[6] += b.z; s[7] += b.w;
    }
#pragma unroll
    for (int j = 0; j < EDD; j++) g_eattr[n * EDD + j] = s[j];
}

__global__ void static_kernel(const float* __restrict__ w_msg, const float* __restrict__ b_msg,
                              const float* __restrict__ b_self) {
    int idx = blockIdx.x * 256 + threadIdx.x;  // grid = N*H exactly (50000 blocks)
    int n = idx >> 7, h = idx & 127;
    int dg = g_deg[n];
    float s = 0.f;
#pragma unroll
    for (int j = 0; j < EDD; j++)
        s += g_eattr[n * EDD + j] * w_msg[(FF + j) * HH + h];
    float inv = 1.f / (float)max(dg, 1);
    g_static[idx] = b_self[h] + (s + (float)dg * b_msg[h]) * inv;
}

__global__ void wcomb_kernel(const float* __restrict__ w_self, const float* __restrict__ w_msg) {
    int idx = blockIdx.x * 256 + threadIdx.x;  // 16384
    int k = idx >> 7, h = idx & 127;
    g_wcomb[idx] = (k < FF) ? w_self[k * HH + h] : w_msg[(k - FF) * HH + h];
}

__global__ void wlstm_kernel(const float* __restrict__ w_ih, const float* __restrict__ w_hh) {
    int idx = blockIdx.x * 256 + threadIdx.x;  // 131072
    int k = idx >> 9, j = idx & 511;
    g_wlstm[idx] = (k < HH) ? w_ih[j * HH + k] : w_hh[j * HH + (k - HH)];
}

// ---------------- per-step gather: warp per node, 16 lanes x float4 per edge ----------------
__global__ __launch_bounds__(256)
void gather_kernel(const float* __restrict__ x, int t) {
    int warp = threadIdx.x >> 5, lane = threadIdx.x & 31;
    int n = blockIdx.x * 8 + warp;          // grid = N/8 = 12500 exact
    int half = lane >> 4;                   // which edge of the pair
    int fl = (lane & 15) << 2;              // 4 features per lane
    int beg = g_rowoff[n], end = g_rowoff[n + 1];
    const float* xb = x + (size_t)t * FF + fl;   // + n*640 per src

    float4 acc = make_float4(0.f, 0.f, 0.f, 0.f);
    int e = beg + half;
    for (; e + 6 < end; e += 8) {
        int s0 = g_csr_src[e];
        int s1 = g_csr_src[e + 2];
        int s2 = g_csr_src[e + 4];
        int s3 = g_csr_src[e + 6];
        float4 v0 = *(const float4*)(xb + (size_t)s0 * (TT * FF));
        float4 v1 = *(const float4*)(xb + (size_t)s1 * (TT * FF));
        float4 v2 = *(const float4*)(xb + (size_t)s2 * (TT * FF));
        float4 v3 = *(const float4*)(xb + (size_t)s3 * (TT * FF));
        acc.x += v0.x + v1.x + v2.x + v3.x;
        acc.y += v0.y + v1.y + v2.y + v3.y;
        acc.z += v0.z + v1.z + v2.z + v3.z;
        acc.w += v0.w + v1.w + v2.w + v3.w;
    }
    for (; e < end; e += 2) {
        int s = g_csr_src[e];
        float4 v = *(const float4*)(xb + (size_t)s * (TT * FF));
        acc.x += v.x; acc.y += v.y; acc.z += v.z; acc.w += v.w;
    }
    acc.x += __shfl_xor_sync(0xffffffffu, acc.x, 16);
    acc.y += __shfl_xor_sync(0xffffffffu, acc.y, 16);
    acc.z += __shfl_xor_sync(0xffffffffu, acc.z, 16);
    acc.w += __shfl_xor_sync(0xffffffffu, acc.w, 16);
    if (half == 0) {
        float inv = 1.f / (float)max(end - beg, 1);
        *(float4*)&g_agg[(size_t)n * FF + fl] =
            make_float4(acc.x * inv, acc.y * inv, acc.z * inv, acc.w * inv);
    }
}

// ---------------- SAGE GEMM + BN stats (streams x_t and g_agg; no indirection) ----------------
#define AS_STR 68

__global__ __launch_bounds__(256)
void sage_gemm_kernel(const float* __restrict__ x, int t, int dummy) {
    __shared__ __align__(16) float As[128 * AS_STR];  // [k][node], 64 nodes
    __shared__ float st[256];
    int tid = threadIdx.x;
    int base = blockIdx.x * 64;
    st[tid] = 0.f;

    {
        int nl = tid >> 2, q = tid & 3;
        int n = base + nl;
        if (n < NN) {
            const float4* xr = (const float4*)(x + (size_t)n * (TT * FF) + t * FF + q * 16);
            const float4* ar = (const float4*)(g_agg + (size_t)n * FF + q * 16);
#pragma unroll
            for (int j = 0; j < 4; j++) {
                float4 v = xr[j];
                int k = q * 16 + j * 4;
                As[(k + 0) * AS_STR + nl] = v.x;
                As[(k + 1) * AS_STR + nl] = v.y;
                As[(k + 2) * AS_STR + nl] = v.z;
                As[(k + 3) * AS_STR + nl] = v.w;
            }
#pragma unroll
            for (int j = 0; j < 4; j++) {
                float4 v = ar[j];
                int k = 64 + q * 16 + j * 4;
                As[(k + 0) * AS_STR + nl] = v.x;
                As[(k + 1) * AS_STR + nl] = v.y;
                As[(k + 2) * AS_STR + nl] = v.z;
                As[(k + 3) * AS_STR + nl] = v.w;
            }
        } else {
#pragma unroll
            for (int j = 0; j < 16; j++) {
                As[(q * 16 + j) * AS_STR + nl] = 0.f;
                As[(64 + q * 16 + j) * AS_STR + nl] = 0.f;
            }
        }
    }
    __syncthreads();

    const int cg = tid & 15;
    const int ng = tid >> 4;
    unsigned long long acc[4][4];
#pragma unroll
    for (int i = 0; i < 4; i++)
#pragma unroll
        for (int m = 0; m < 4; m++) acc[i][m] = 0ULL;

#pragma unroll 4
    for (int k = 0; k < 128; k++) {
        float4 av = *(const float4*)&As[k * AS_STR + (ng << 2)];
        const ulonglong2* wp = (const ulonglong2*)&g_wcomb[(k << 7) + (cg << 3)];
        ulonglong2 wA = wp[0], wB = wp[1];
        unsigned long long a0 = pk2(av.x, av.x);
        unsigned long long a1 = pk2(av.y, av.y);
        unsigned long long a2 = pk2(av.z, av.z);
        unsigned long long a3 = pk2(av.w, av.w);
        acc[0][0] = ffma2(a0, wA.x, acc[0][0]); acc[0][1] = ffma2(a0, wA.y, acc[0][1]);
        acc[0][2] = ffma2(a0, wB.x, acc[0][2]); acc[0][3] = ffma2(a0, wB.y, acc[0][3]);
        acc[1][0] = ffma2(a1, wA.x, acc[1][0]); acc[1][1] = ffma2(a1, wA.y, acc[1][1]);
        acc[1][2] = ffma2(a1, wB.x, acc[1][2]); acc[1][3] = ffma2(a1, wB.y, acc[1][3]);
        acc[2][0] = ffma2(a2, wA.x, acc[2][0]); acc[2][1] = ffma2(a2, wA.y, acc[2][1]);
        acc[2][2] = ffma2(a2, wB.x, acc[2][2]); acc[2][3] = ffma2(a2, wB.y, acc[2][3]);
        acc[3][0] = ffma2(a3, wA.x, acc[3][0]); acc[3][1] = ffma2(a3, wA.y, acc[3][1]);
        acc[3][2] = ffma2(a3, wB.x, acc[3][2]); acc[3][3] = ffma2(a3, wB.y, acc[3][3]);
    }

    float vsum[8], vsq[8];
#pragma unroll
    for (int j = 0; j < 8; j++) { vsum[j] = 0.f; vsq[j] = 0.f; }
#pragma unroll
    for (int i = 0; i < 4; i++) {
        int n = base + (ng << 2) + i;
        if (n < NN) {
            float v[8];
            upk2(acc[i][0], v[0], v[1]);
            upk2(acc[i][1], v[2], v[3]);
            upk2(acc[i][2], v[4], v[5]);
            upk2(acc[i][3], v[6], v[7]);
            const float4* sp = (const float4*)&g_static[(size_t)n * HH + (cg << 3)];
            float4 sA = sp[0], sB = sp[1];
            v[0] += sA.x; v[1] += sA.y; v[2] += sA.z; v[3] += sA.w;
            v[4] += sB.x; v[5] += sB.y; v[6] += sB.z; v[7] += sB.w;
#pragma unroll
            for (int j = 0; j < 8; j++) { vsum[j] += v[j]; vsq[j] += v[j] * v[j]; }
        }
    }
#pragma unroll
    for (int j = 0; j < 8; j++) {
        atomicAdd(&st[(cg << 3) + j], vsum[j]);
        atomicAdd(&st[128 + (cg << 3) + j], vsq[j]);
    }
    __syncthreads();
    float* stats = dummy ? g_stats_dummy : g_stats;
    atomicAdd(&stats[tid], st[tid]);
}

// ---------------- BN finalize (also resets stats for next step/replay) ----------------
__global__ void bn_finalize_kernel(const float* __restrict__ gamma, const float* __restrict__ beta) {
    int h = threadIdx.x;  // 128 threads
    float m = g_stats[h] / (float)NN;
    float var = g_stats[128 + h] / (float)NN - m * m;
    float sc = gamma[h] * rsqrtf(var + BN_EPS);
    g_bnscale[h] = sc;
    g_bnshift[h] = beta[h] - m * sc;
    g_stats[h] = 0.f;
    g_stats[128 + h] = 0.f;
}

// ---------------- focal rows: recompute out from g_agg, apply BN+ReLU ----------------
__global__ __launch_bounds__(256)
void focal_kernel(const float* __restrict__ x, const int* __restrict__ ptr, int t) {
    __shared__ __align__(16) float As[128 * 9];  // [k][row], 8 rows
    int tid = threadIdx.x;
    int warp = tid >> 5, lane = tid & 31;

    {
        int b = blockIdx.x * 8 + warp;  // < 2048
        int n = ptr[b];
        const float* xr = x + (size_t)n * (TT * FF) + t * FF;
        const float* ar = g_agg + (size_t)n * FF;
        As[lane * 9 + warp] = xr[lane];
        As[(lane + 32) * 9 + warp] = xr[lane + 32];
        As[(lane + 64) * 9 + warp] = ar[lane];
        As[(lane + 96) * 9 + warp] = ar[lane + 32];
    }
    __syncthreads();

    int r = warp;
    int c0 = lane * 4;
    float v0 = 0.f, v1 = 0.f, v2 = 0.f, v3 = 0.f;
#pragma unroll 4
    for (int k = 0; k < 128; k++) {
        float a = As[k * 9 + r];
        float4 w = *(const float4*)&g_wcomb[k * HH + c0];
        v0 += a * w.x; v1 += a * w.y; v2 += a * w.z; v3 += a * w.w;
    }
    int b = blockIdx.x * 8 + r;
    int n = ptr[b];
    const float4 sv = *(const float4*)&g_static[(size_t)n * HH + c0];
    v0 += sv.x; v1 += sv.y; v2 += sv.z; v3 += sv.w;
    v0 = fmaxf(fmaf(v0, g_bnscale[c0 + 0], g_bnshift[c0 + 0]), 0.f);
    v1 = fmaxf(fmaf(v1, g_bnscale[c0 + 1], g_bnshift[c0 + 1]), 0.f);
    v2 = fmaxf(fmaf(v2, g_bnscale[c0 + 2], g_bnshift[c0 + 2]), 0.f);
    v3 = fmaxf(fmaf(v3, g_bnscale[c0 + 3], g_bnshift[c0 + 3]), 0.f);
    *(float4*)&g_hseq[((size_t)t * BB + b) * HH + c0] = make_float4(v0, v1, v2, v3);
}

// ---------------- LSTM: gates GEMM (K=256 concat), packed f32x2 ----------------
__global__ __launch_bounds__(256)
void lstm_gemm_kernel(int t) {
    __shared__ __align__(16) float As[256 * 17];  // [k][16 rows pad17]
    int tid = threadIdx.x;
    int bb = blockIdx.x * 16;  // grid = 128

    {
        int row = tid >> 4;
        int kk = tid & 15;
        int b = bb + row;
        const float* hin = &g_hseq[((size_t)t * BB + b) * HH];
        const float* hpr = &g_h[(size_t)b * HH];
#pragma unroll
        for (int m = 0; m < 16; m++) {
            int k = kk + 16 * m;
            As[k * 17 + row] = (k < HH) ? hin[k] : hpr[k - HH];
        }
    }
    __syncthreads();

    int jg = tid & 31;   // gates jg*16 .. +15
    int bg = tid >> 5;   // batches bg*2, bg*2+1
    int j0 = jg * 16;
    unsigned long long acc[2][8];
#pragma unroll
    for (int i = 0; i < 2; i++)
#pragma unroll
        for (int m = 0; m < 8; m++) acc[i][m] = 0ULL;

#pragma unroll 2
    for (int k = 0; k < 256; k++) {
        float a0 = As[k * 17 + bg * 2];
        float a1 = As[k * 17 + bg * 2 + 1];
        const ulonglong2* Wp = (const ulonglong2*)&g_wlstm[(size_t)k * 512 + j0];
        ulonglong2 w0 = Wp[0], w1 = Wp[1], w2 = Wp[2], w3 = Wp[3];
        unsigned long long p0 = pk2(a0, a0);
        unsigned long long p1 = pk2(a1, a1);
        acc[0][0] = ffma2(p0, w0.x, acc[0][0]); acc[0][1] = ffma2(p0, w0.y, acc[0][1]);
        acc[0][2] = ffma2(p0, w1.x, acc[0][2]); acc[0][3] = ffma2(p0, w1.y, acc[0][3]);
        acc[0][4] = ffma2(p0, w2.x, acc[0][4]); acc[0][5] = ffma2(p0, w2.y, acc[0][5]);
        acc[0][6] = ffma2(p0, w3.x, acc[0][6]); acc[0][7] = ffma2(p0, w3.y, acc[0][7]);
        acc[1][0] = ffma2(p1, w0.x, acc[1][0]); acc[1][1] = ffma2(p1, w0.y, acc[1][1]);
        acc[1][2] = ffma2(p1, w1.x, acc[1][2]); acc[1][3] = ffma2(p1, w1.y, acc[1][3]);
        acc[1][4] = ffma2(p1, w2.x, acc[1][4]); acc[1][5] = ffma2(p1, w2.y, acc[1][5]);
        acc[1][6] = ffma2(p1, w3.x, acc[1][6]); acc[1][7] = ffma2(p1, w3.y, acc[1][7]);
    }

#pragma unroll
    for (int i = 0; i < 2; i++) {
        int b = bb + bg * 2 + i;
        float v[16];
#pragma unroll
        for (int m = 0; m < 8; m++) upk2(acc[i][m], v[2 * m], v[2 * m + 1]);
        float4* gp = (float4*)&g_gates[(size_t)b * 512 + j0];
        gp[0] = make_float4(v[0],  v[1],  v[2],  v[3]);
        gp[1] = make_float4(v[4],  v[5],  v[6],  v[7]);
        gp[2] = make_float4(v[8],  v[9],  v[10], v[11]);
        gp[3] = make_float4(v[12], v[13], v[14], v[15]);
    }
}

__device__ __forceinline__ float sigm(float x) { return 1.f / (1.f + expf(-x)); }

__global__ void lstm_elem_kernel(const float* __restrict__ b_ih, const float* __restrict__ b_hh) {
    int idx = blockIdx.x * 256 + threadIdx.x;  // B*H = 262144
    int b = idx >> 7, h = idx & 127;
    const float* gr = &g_gates[(size_t)b * 512];
    float gi = gr[h]        + b_ih[h]        + b_hh[h];
    float gf = gr[128 + h]  + b_ih[128 + h]  + b_hh[128 + h];
    float gg = gr[256 + h]  + b_ih[256 + h]  + b_hh[256 + h];
    float go = gr[384 + h]  + b_ih[384 + h]  + b_hh[384 + h];
    float i_ = sigm(gi), f_ = sigm(gf), o_ = sigm(go);
    float g_ = tanhf(gg);
    float c = f_ * g_c[idx] + i_ * g_;
    g_c[idx] = c;
    g_h[idx] = o_ * tanhf(c);
}

// ---------------- classifier ----------------
__global__ void cls_kernel(const float* __restrict__ w_cls, const float* __restrict__ b_cls,
                           float* __restrict__ out) {
    int idx = blockIdx.x * 256 + threadIdx.x;  // B*C = 4096
    int b = idx >> 1, c = idx & 1;
    float s = b_cls[c];
    const float* hr = &g_h[(size_t)b * HH];
#pragma unroll 8
    for (int k = 0; k < HH; k++) s += hr[k] * w_cls[k * CC + c];
    out[idx] = s;
}

// ---------------- launch ----------------
extern "C" void kernel_launch(void* const* d_in, const int* in_sizes, int n_in,
                              void* d_out, int out_size) {
    const float* x      = (const float*)d_in[0];
    const int*   ei     = (const int*)d_in[1];     // int32 (JAX x64 disabled)
    const float* eattr  = (const float*)d_in[2];
    const int*   ptr    = (const int*)d_in[3];     // int32
    const float* w_msg  = (const float*)d_in[4];
    const float* b_msg  = (const float*)d_in[5];
    const float* w_self = (const float*)d_in[6];
    const float* b_self = (const float*)d_in[7];
    const float* gamma  = (const float*)d_in[8];
    const float* beta   = (const float*)d_in[9];
    const float* w_ih   = (const float*)d_in[10];
    const float* w_hh   = (const float*)d_in[11];
    const float* b_ih   = (const float*)d_in[12];
    const float* b_hh   = (const float*)d_in[13];
    const float* w_cls  = (const float*)d_in[14];
    const float* b_cls  = (const float*)d_in[15];
    float* out = (float*)d_out;

    const int sage_blocks = (NN + 63) / 64;  // 1563

    zero_kernel<<<(BB * HH) / 256, 256>>>();             // 1
    deg_kernel<<<EE / 256, 256>>>(ei);                   // 2
    scan_kernel<<<1, 1024>>>();                          // 3
    // ---- diagnostic dummy launches (positions 4-6, ncu capture window) ----
    // Correctness-neutral: outputs overwritten / routed to g_stats_dummy.
    gather_kernel<<<NN / 8, 256>>>(x, 0);                // 4: profiled gather
    sage_gemm_kernel<<<sage_blocks, 256>>>(x, 0, 1);     // 5: profiled sage GEMM (dummy stats)
    lstm_gemm_kernel<<<BB / 16, 256>>>(0);               // 6: profiled lstm GEMM
    // ---- real prep ----
    fill_kernel<<<EE / 256, 256>>>(ei);                  // 7
    eattr_kernel<<<(NN + 255) / 256, 256>>>(eattr);
    static_kernel<<<(NN * HH) / 256, 256>>>(w_msg, b_msg, b_self);
    wcomb_kernel<<<(128 * 128) / 256, 256>>>(w_self, w_msg);
    wlstm_kernel<<<(256 * 512) / 256, 256>>>(w_ih, w_hh);

    for (int t = 0; t < TT; t++) {
        gather_kernel<<<NN / 8, 256>>>(x, t);
        sage_gemm_kernel<<<sage_blocks, 256>>>(x, t, 0);
        bn_finalize_kernel<<<1, 128>>>(gamma, beta);
        focal_kernel<<<BB / 8, 256>>>(x, ptr, t);
    }
    for (int t = 0; t < TT; t++) {
        lstm_gemm_kernel<<<BB / 16, 256>>>(t);
        lstm_elem_kernel<<<(BB * HH) / 256, 256>>>(b_ih, b_hh);
    }
    cls_kernel<<<(BB * CC) / 256, 256>>>(w_cls, b_cls, out);
}

// round 14
// speedup vs baseline: 1.9664x; 1.9664x over previous
#include <cuda_runtime.h>
#include <cstdint>

#define NN   100000
#define TT   10
#define FF   64
#define EE   1600000
#define EDD  8
#define HH   128
#define BB   2048
#define CC   2
#define BN_EPS 1e-5f

// ---------------- device scratch (no allocations allowed) ----------------
__device__ __align__(16) float g_wcomb[128 * 128];             // [k][h]
__device__ __align__(16) float g_wlstm[256 * 512];             // [k][j] concat(w_ih,w_hh)^T
__device__ __align__(16) float g_static[(size_t)NN * HH];      // time-invariant term
__device__ __align__(16) float g_eattr[NN * EDD];              // per-node edge_attr sums (atomic)
__device__ __align__(16) float g_agg[(size_t)NN * TT * FF];    // agg for ALL t, layout [n][t][64] (mirrors x)
__device__ int   g_deg[NN];
__device__ int   g_rowoff[NN + 1];
__device__ int   g_cursor[NN];
__device__ int   g_csr_src[EE];
__device__ float g_stats_t[TT * 2 * HH];                       // per-t sum/sumsq
__device__ __align__(16) float g_hseq[(size_t)TT * BB * HH];
__device__ __align__(16) float g_h[BB * HH];
__device__ __align__(16) float g_c[BB * HH];

// ---------------- f32x2 packed-FMA helpers ----------------
__device__ __forceinline__ unsigned long long pk2(float a, float b) {
    unsigned long long r;
    asm("mov.b64 %0, {%1, %2};" : "=l"(r) : "f"(a), "f"(b));
    return r;
}
__device__ __forceinline__ unsigned long long ffma2(unsigned long long a, unsigned long long b,
                                                    unsigned long long c) {
    unsigned long long d;
    asm("fma.rn.f32x2 %0, %1, %2, %3;" : "=l"(d) : "l"(a), "l"(b), "l"(c));
    return d;
}
__device__ __forceinline__ void upk2(unsigned long long v, float& a, float& b) {
    asm("mov.b64 {%0, %1}, %2;" : "=f"(a), "=f"(b) : "l"(v));
}

// ---------------- prep ----------------
__global__ void zero_kernel() {
    int i = blockIdx.x * 256 + threadIdx.x;   // grid 3125 -> 800000 = NN*EDD
    g_eattr[i] = 0.f;
    if (i < NN) { g_deg[i] = 0; g_cursor[i] = 0; }
    if (i < BB * HH) { g_h[i] = 0.f; g_c[i] = 0.f; }
    if (i < TT * 2 * HH) g_stats_t[i] = 0.f;
}

// per-edge: degree count + edge_attr scatter-sum (8 float atomics, spread addresses)
__global__ void edge_prep_kernel(const int* __restrict__ ei, const float* __restrict__ eattr) {
    int e = blockIdx.x * 256 + threadIdx.x;   // grid = E exactly
    int d = ei[EE + e];
    atomicAdd(&g_deg[d], 1);
    const float4* p = (const float4*)(eattr + (size_t)e * EDD);
    float4 a = p[0], b = p[1];
    float* dst = &g_eattr[d * EDD];
    atomicAdd(dst + 0, a.x); atomicAdd(dst + 1, a.y);
    atomicAdd(dst + 2, a.z); atomicAdd(dst + 3, a.w);
    atomicAdd(dst + 4, b.x); atomicAdd(dst + 5, b.y);
    atomicAdd(dst + 6, b.z); atomicAdd(dst + 7, b.w);
}

__global__ void scan_kernel() {  // 1 block, 1024 threads
    const int CH = (NN + 1023) / 1024;  // 98
    int t = threadIdx.x;
    int beg = t * CH;
    int end = min(beg + CH, NN);
    int s = 0;
    for (int i = beg; i < end; i++) s += g_deg[i];
    __shared__ int ps[1024];
    ps[t] = s;
    __syncthreads();
    for (int off = 1; off < 1024; off <<= 1) {
        int v = (t >= off) ? ps[t - off] : 0;
        __syncthreads();
        ps[t] += v;
        __syncthreads();
    }
    int run = ps[t] - s;
    for (int i = beg; i < end; i++) { g_rowoff[i] = run; run += g_deg[i]; }
    if (t == 1023) g_rowoff[NN] = ps[1023];
}

__global__ void fill_kernel(const int* __restrict__ ei) {
    int e = blockIdx.x * 256 + threadIdx.x;  // grid = E exactly
    int d = ei[EE + e];
    int pos = g_rowoff[d] + atomicAdd(&g_cursor[d], 1);
    g_csr_src[pos] = ei[e];
}

__global__ void static_kernel(const float* __restrict__ w_msg, const float* __restrict__ b_msg,
                              const float* __restrict__ b_self) {
    int idx = blockIdx.x * 256 + threadIdx.x;  // grid = N*H exactly
    int n = idx >> 7, h = idx & 127;
    int dg = g_deg[n];
    float s = 0.f;
#pragma unroll
    for (int j = 0; j < EDD; j++)
        s += g_eattr[n * EDD + j] * w_msg[(FF + j) * HH + h];
    float inv = 1.f / (float)max(dg, 1);
    g_static[idx] = b_self[h] + (s + (float)dg * b_msg[h]) * inv;
}

__global__ void wcomb_kernel(const float* __restrict__ w_self, const float* __restrict__ w_msg) {
    int idx = blockIdx.x * 256 + threadIdx.x;  // 16384
    int k = idx >> 7, h = idx & 127;
    g_wcomb[idx] = (k < FF) ? w_self[k * HH + h] : w_msg[(k - FF) * HH + h];
}

__global__ void wlstm_kernel(const float* __restrict__ w_ih, const float* __restrict__ w_hh) {
    int idx = blockIdx.x * 256 + threadIdx.x;  // 131072
    int k = idx >> 9, j = idx & 511;
    g_wlstm[idx] = (k < HH) ? w_ih[j * HH + k] : w_hh[j * HH + (k - HH)];
}

// ---------------- gather for 5 time-steps at once (launch twice: tc=0, tc=5) ----------------
__global__ __launch_bounds__(256)
void gather5_kernel(const float* __restrict__ x, int tc) {
    int warp = threadIdx.x >> 5, lane = threadIdx.x & 31;
    int n = blockIdx.x * 8 + warp;          // grid = N/8 = 12500 exact
    int half = lane >> 4;
    int fl = (lane & 15) << 2;              // 4 features per lane
    int beg = g_rowoff[n], end = g_rowoff[n + 1];
    const float* xb = x + tc * FF + fl;     // + src*640

    float4 a0 = make_float4(0.f, 0.f, 0.f, 0.f);
    float4 a1 = a0, a2 = a0, a3 = a0, a4 = a0;
    for (int e = beg + half; e < end; e += 2) {
        int src = g_csr_src[e];
        const float4* p = (const float4*)(xb + (size_t)src * (TT * FF));
        float4 v0 = p[0];        // t = tc+0  (offset 0   floats)
        float4 v1 = p[16];       // t = tc+1  (offset 64)
        float4 v2 = p[32];
        float4 v3 = p[48];
        float4 v4 = p[64];
        a0.x += v0.x; a0.y += v0.y; a0.z += v0.z; a0.w += v0.w;
        a1.x += v1.x; a1.y += v1.y; a1.z += v1.z; a1.w += v1.w;
        a2.x += v2.x; a2.y += v2.y; a2.z += v2.z; a2.w += v2.w;
        a3.x += v3.x; a3.y += v3.y; a3.z += v3.z; a3.w += v3.w;
        a4.x += v4.x; a4.y += v4.y; a4.z += v4.z; a4.w += v4.w;
    }
    // combine the two halves
#define RED(f) f = f + __shfl_xor_sync(0xffffffffu, f, 16)
    RED(a0.x); RED(a0.y); RED(a0.z); RED(a0.w);
    RED(a1.x); RED(a1.y); RED(a1.z); RED(a1.w);
    RED(a2.x); RED(a2.y); RED(a2.z); RED(a2.w);
    RED(a3.x); RED(a3.y); RED(a3.z); RED(a3.w);
    RED(a4.x); RED(a4.y); RED(a4.z); RED(a4.w);
#undef RED
    if (half == 0) {
        float inv = 1.f / (float)max(end - beg, 1);
        float* ob = &g_agg[(size_t)n * (TT * FF) + tc * FF + fl];
        *(float4*)(ob +   0) = make_float4(a0.x * inv, a0.y * inv, a0.z * inv, a0.w * inv);
        *(float4*)(ob +  64) = make_float4(a1.x * inv, a1.y * inv, a1.z * inv, a1.w * inv);
        *(float4*)(ob + 128) = make_float4(a2.x * inv, a2.y * inv, a2.z * inv, a2.w * inv);
        *(float4*)(ob + 192) = make_float4(a3.x * inv, a3.y * inv, a3.z * inv, a3.w * inv);
        *(float4*)(ob + 256) = make_float4(a4.x * inv, a4.y * inv, a4.z * inv, a4.w * inv);
    }
}

// ---------------- SAGE GEMM + BN stats for ALL t (grid 1563 x 10) ----------------
#define AS_STR 68

__global__ __launch_bounds__(256)
void sage_all_kernel(const float* __restrict__ x) {
    __shared__ __align__(16) float As[128 * AS_STR];  // [k][node], 64 nodes
    __shared__ float st[256];
    int tid = threadIdx.x;
    int t = blockIdx.y;
    int base = blockIdx.x * 64;
    st[tid] = 0.f;

    // load phase: thread -> (node nl, quarter q): 16 floats of x_t + 16 of agg_t
    {
        int nl = tid >> 2, q = tid & 3;
        int n = base + nl;
        if (n < NN) {
            const float4* xr = (const float4*)(x + (size_t)n * (TT * FF) + t * FF + q * 16);
            const float4* ar = (const float4*)(g_agg + (size_t)n * (TT * FF) + t * FF + q * 16);
#pragma unroll
            for (int j = 0; j < 4; j++) {
                float4 v = xr[j];
                int k = q * 16 + j * 4;
                As[(k + 0) * AS_STR + nl] = v.x;
                As[(k + 1) * AS_STR + nl] = v.y;
                As[(k + 2) * AS_STR + nl] = v.z;
                As[(k + 3) * AS_STR + nl] = v.w;
            }
#pragma unroll
            for (int j = 0; j < 4; j++) {
                float4 v = ar[j];
                int k = 64 + q * 16 + j * 4;
                As[(k + 0) * AS_STR + nl] = v.x;
                As[(k + 1) * AS_STR + nl] = v.y;
                As[(k + 2) * AS_STR + nl] = v.z;
                As[(k + 3) * AS_STR + nl] = v.w;
            }
        } else {
#pragma unroll
            for (int j = 0; j < 16; j++) {
                As[(q * 16 + j) * AS_STR + nl] = 0.f;
                As[(64 + q * 16 + j) * AS_STR + nl] = 0.f;
            }
        }
    }
    __syncthreads();

    // warp tile: 32 ch x 32 nodes -> per-warp W read = 128B/k (was 512B+)
    int warp = tid >> 5, lane = tid & 31;
    int nodeoff = (warp & 1) * 32 + (lane >> 2) * 4;   // 0..60
    int choff   = (warp >> 1) * 32 + (lane & 3) * 8;   // 0..120
    unsigned long long acc[4][4];
#pragma unroll
    for (int i = 0; i < 4; i++)
#pragma unroll
        for (int m = 0; m < 4; m++) acc[i][m] = 0ULL;

#pragma unroll 4
    for (int k = 0; k < 128; k++) {
        float4 av = *(const float4*)&As[k * AS_STR + nodeoff];
        const ulonglong2* wp = (const ulonglong2*)&g_wcomb[(k << 7) + choff];
        ulonglong2 wA = wp[0], wB = wp[1];
        unsigned long long b0 = pk2(av.x, av.x);
        unsigned long long b1 = pk2(av.y, av.y);
        unsigned long long b2 = pk2(av.z, av.z);
        unsigned long long b3 = pk2(av.w, av.w);
        acc[0][0] = ffma2(b0, wA.x, acc[0][0]); acc[0][1] = ffma2(b0, wA.y, acc[0][1]);
        acc[0][2] = ffma2(b0, wB.x, acc[0][2]); acc[0][3] = ffma2(b0, wB.y, acc[0][3]);
        acc[1][0] = ffma2(b1, wA.x, acc[1][0]); acc[1][1] = ffma2(b1, wA.y, acc[1][1]);
        acc[1][2] = ffma2(b1, wB.x, acc[1][2]); acc[1][3] = ffma2(b1, wB.y, acc[1][3]);
        acc[2][0] = ffma2(b2, wA.x, acc[2][0]); acc[2][1] = ffma2(b2, wA.y, acc[2][1]);
        acc[2][2] = ffma2(b2, wB.x, acc[2][2]); acc[2][3] = ffma2(b2, wB.y, acc[2][3]);
        acc[3][0] = ffma2(b3, wA.x, acc[3][0]); acc[3][1] = ffma2(b3, wA.y, acc[3][1]);
        acc[3][2] = ffma2(b3, wB.x, acc[3][2]); acc[3][3] = ffma2(b3, wB.y, acc[3][3]);
    }

    // epilogue: + static, BN sum/sumsq only
    float vsum[8], vsq[8];
#pragma unroll
    for (int j = 0; j < 8; j++) { vsum[j] = 0.f; vsq[j] = 0.f; }
#pragma unroll
    for (int i = 0; i < 4; i++) {
        int n = base + nodeoff + i;
        if (n < NN) {
            float v[8];
            upk2(acc[i][0], v[0], v[1]);
            upk2(acc[i][1], v[2], v[3]);
            upk2(acc[i][2], v[4], v[5]);
            upk2(acc[i][3], v[6], v[7]);
            const float4* sp = (const float4*)&g_static[(size_t)n * HH + choff];
            float4 sA = sp[0], sB = sp[1];
            v[0] += sA.x; v[1] += sA.y; v[2] += sA.z; v[3] += sA.w;
            v[4] += sB.x; v[5] += sB.y; v[6] += sB.z; v[7] += sB.w;
#pragma unroll
            for (int j = 0; j < 8; j++) { vsum[j] += v[j]; vsq[j] += v[j] * v[j]; }
        }
    }
#pragma unroll
    for (int j = 0; j < 8; j++) {
        atomicAdd(&st[choff + j], vsum[j]);
        atomicAdd(&st[128 + choff + j], vsq[j]);
    }
    __syncthreads();
    atomicAdd(&g_stats_t[t * 256 + tid], st[tid]);
}

// ---------------- focal rows for ALL t: BN finalize in-block + GEMM + ReLU ----------------
__global__ __launch_bounds__(256)
void focal_all_kernel(const float* __restrict__ x, const int* __restrict__ ptr,
                      const float* __restrict__ gamma, const float* __restrict__ beta) {
    __shared__ __align__(16) float As[128 * 9];
    __shared__ float s_sc[128], s_sh[128];
    int tid = threadIdx.x;
    int t = blockIdx.y;
    int warp = tid >> 5, lane = tid & 31;

    if (tid < 128) {
        float m = g_stats_t[t * 256 + tid] / (float)NN;
        float var = g_stats_t[t * 256 + 128 + tid] / (float)NN - m * m;
        float sc = gamma[tid] * rsqrtf(var + BN_EPS);
        s_sc[tid] = sc;
        s_sh[tid] = beta[tid] - m * sc;
    }
    {
        int b = blockIdx.x * 8 + warp;  // < 2048
        int n = ptr[b];
        const float* xr = x + (size_t)n * (TT * FF) + t * FF;
        const float* ar = g_agg + (size_t)n * (TT * FF) + t * FF;
        As[lane * 9 + warp] = xr[lane];
        As[(lane + 32) * 9 + warp] = xr[lane + 32];
        As[(lane + 64) * 9 + warp] = ar[lane];
        As[(lane + 96) * 9 + warp] = ar[lane + 32];
    }
    __syncthreads();

    int r = warp;
    int c0 = lane * 4;
    float v0 = 0.f, v1 = 0.f, v2 = 0.f, v3 = 0.f;
#pragma unroll 4
    for (int k = 0; k < 128; k++) {
        float a = As[k * 9 + r];
        float4 w = *(const float4*)&g_wcomb[k * HH + c0];
        v0 += a * w.x; v1 += a * w.y; v2 += a * w.z; v3 += a * w.w;
    }
    int b = blockIdx.x * 8 + r;
    int n = ptr[b];
    const float4 sv = *(const float4*)&g_static[(size_t)n * HH + c0];
    v0 += sv.x; v1 += sv.y; v2 += sv.z; v3 += sv.w;
    v0 = fmaxf(fmaf(v0, s_sc[c0 + 0], s_sh[c0 + 0]), 0.f);
    v1 = fmaxf(fmaf(v1, s_sc[c0 + 1], s_sh[c0 + 1]), 0.f);
    v2 = fmaxf(fmaf(v2, s_sc[c0 + 2], s_sh[c0 + 2]), 0.f);
    v3 = fmaxf(fmaf(v3, s_sc[c0 + 3], s_sh[c0 + 3]), 0.f);
    *(float4*)&g_hseq[((size_t)t * BB + b) * HH + c0] = make_float4(v0, v1, v2, v3);
}

// ---------------- fused LSTM step: gates GEMM + nonlinearity + h/c update ----------------
__device__ __forceinline__ float sigm(float x) { return 1.f / (1.f + expf(-x)); }

__global__ __launch_bounds__(256)
void lstm_step_kernel(int t, const float* __restrict__ b_ih, const float* __restrict__ b_hh) {
    __shared__ __align__(16) float sm[16 * 516];   // As (256*17=4352 floats) then gates [16][516]
    __shared__ float bias[512];
    int tid = threadIdx.x;
    int bb = blockIdx.x * 16;  // grid = 128

    bias[tid] = b_ih[tid] + b_hh[tid];
    bias[tid + 256] = b_ih[tid + 256] + b_hh[tid + 256];

    {   // As load: [k][16 rows pad17]
        int row = tid >> 4;
        int kk = tid & 15;
        int b = bb + row;
        const float* hin = &g_hseq[((size_t)t * BB + b) * HH];
        const float* hpr = &g_h[(size_t)b * HH];
#pragma unroll
        for (int m = 0; m < 16; m++) {
            int k = kk + 16 * m;
            sm[k * 17 + row] = (k < HH) ? hin[k] : hpr[k - HH];
        }
    }
    __syncthreads();

    int jg = tid & 31;   // gates jg*16 .. +15
    int bg = tid >> 5;   // batches bg*2, bg*2+1
    int j0 = jg * 16;
    unsigned long long acc[2][8];
#pragma unroll
    for (int i = 0; i < 2; i++)
#pragma unroll
        for (int m = 0; m < 8; m++) acc[i][m] = 0ULL;

#pragma unroll 2
    for (int k = 0; k < 256; k++) {
        float a0 = sm[k * 17 + bg * 2];
        float a1 = sm[k * 17 + bg * 2 + 1];
        const ulonglong2* Wp = (const ulonglong2*)&g_wlstm[(size_t)k * 512 + j0];
        ulonglong2 w0 = Wp[0], w1 = Wp[1], w2 = Wp[2], w3 = Wp[3];
        unsigned long long p0 = pk2(a0, a0);
        unsigned long long p1 = pk2(a1, a1);
        acc[0][0] = ffma2(p0, w0.x, acc[0][0]); acc[0][1] = ffma2(p0, w0.y, acc[0][1]);
        acc[0][2] = ffma2(p0, w1.x, acc[0][2]); acc[0][3] = ffma2(p0, w1.y, acc[0][3]);
        acc[0][4] = ffma2(p0, w2.x, acc[0][4]); acc[0][5] = ffma2(p0, w2.y, acc[0][5]);
        acc[0][6] = ffma2(p0, w3.x, acc[0][6]); acc[0][7] = ffma2(p0, w3.y, acc[0][7]);
        acc[1][0] = ffma2(p1, w0.x, acc[1][0]); acc[1][1] = ffma2(p1, w0.y, acc[1][1]);
        acc[1][2] = ffma2(p1, w1.x, acc[1][2]); acc[1][3] = ffma2(p1, w1.y, acc[1][3]);
        acc[1][4] = ffma2(p1, w2.x, acc[1][4]); acc[1][5] = ffma2(p1, w2.y, acc[1][5]);
        acc[1][6] = ffma2(p1, w3.x, acc[1][6]); acc[1][7] = ffma2(p1, w3.y, acc[1][7]);
    }
    __syncthreads();   // all warps done reading As before gates overwrite sm

#pragma unroll
    for (int i = 0; i < 2; i++) {
        int row = bg * 2 + i;
        float v[16];
#pragma unroll
        for (int m = 0; m < 8; m++) upk2(acc[i][m], v[2 * m], v[2 * m + 1]);
#pragma unroll
        for (int m = 0; m < 16; m++) sm[row * 516 + j0 + m] = v[m];
    }
    __syncthreads();

    // update: 8 (row,h) pairs per thread
#pragma unroll
    for (int m = 0; m < 8; m++) {
        int gid = tid + 256 * m;       // < 2048
        int r = gid >> 7, h = gid & 127;
        const float* gr = &sm[r * 516];
        float gi = gr[h]       + bias[h];
        float gf = gr[128 + h] + bias[128 + h];
        float gg = gr[256 + h] + bias[256 + h];
        float go = gr[384 + h] + bias[384 + h];
        float i_ = sigm(gi), f_ = sigm(gf), o_ = sigm(go);
        float g_ = tanhf(gg);
        size_t gix = (size_t)(bb + r) * HH + h;
        float c = f_ * g_c[gix] + i_ * g_;
        g_c[gix] = c;
        g_h[gix] = o_ * tanhf(c);
    }
}

// ---------------- classifier ----------------
__global__ void cls_kernel(const float* __restrict__ w_cls, const float* __restrict__ b_cls,
                           float* __restrict__ out) {
    int idx = blockIdx.x * 256 + threadIdx.x;  // B*C = 4096
    int b = idx >> 1, c = idx & 1;
    float s = b_cls[c];
    const float* hr = &g_h[(size_t)b * HH];
#pragma unroll 8
    for (int k = 0; k < HH; k++) s += hr[k] * w_cls[k * CC + c];
    out[idx] = s;
}

// ---------------- launch ----------------
extern "C" void kernel_launch(void* const* d_in, const int* in_sizes, int n_in,
                              void* d_out, int out_size) {
    const float* x      = (const float*)d_in[0];
    const int*   ei     = (const int*)d_in[1];     // int32 (JAX x64 disabled)
    const float* eattr  = (const float*)d_in[2];
    const int*   ptr    = (const int*)d_in[3];     // int32
    const float* w_msg  = (const float*)d_in[4];
    const float* b_msg  = (const float*)d_in[5];
    const float* w_self = (const float*)d_in[6];
    const float* b_self = (const float*)d_in[7];
    const float* gamma  = (const float*)d_in[8];
    const float* beta   = (const float*)d_in[9];
    const float* w_ih   = (const float*)d_in[10];
    const float* w_hh   = (const float*)d_in[11];
    const float* b_ih   = (const float*)d_in[12];
    const float* b_hh   = (const float*)d_in[13];
    const float* w_cls  = (const float*)d_in[14];
    const float* b_cls  = (const float*)d_in[15];
    float* out = (float*)d_out;

    zero_kernel<<<(NN * EDD) / 256, 256>>>();            // 1
    edge_prep_kernel<<<EE / 256, 256>>>(ei, eattr);      // 2
    scan_kernel<<<1, 1024>>>();                          // 3
    fill_kernel<<<EE / 256, 256>>>(ei);                  // 4
    static_kernel<<<(NN * HH) / 256, 256>>>(w_msg, b_msg, b_self);  // 5
    gather5_kernel<<<NN / 8, 256>>>(x, 0);               // 6  <- ncu capture slot (real data)
    gather5_kernel<<<NN / 8, 256>>>(x, 5);               // 7
    wcomb_kernel<<<(128 * 128) / 256, 256>>>(w_self, w_msg);
    wlstm_kernel<<<(256 * 512) / 256, 256>>>(w_ih, w_hh);

    dim3 sg((NN + 63) / 64, TT);                         // 1563 x 10
    sage_all_kernel<<<sg, 256>>>(x);
    dim3 fg(BB / 8, TT);                                 // 256 x 10
    focal_all_kernel<<<fg, 256>>>(x, ptr, gamma, beta);

    for (int t = 0; t < TT; t++)
        lstm_step_kernel<<<BB / 16, 256>>>(t, b_ih, b_hh);
    cls_kernel<<<(BB * CC) / 256, 256>>>(w_cls, b_cls, out);
}